// round 3
// baseline (speedup 1.0000x reference)
#include <cuda_runtime.h>
#include <cuda_bf16.h>

// HolographicLayer: eta = dot(R[p], ccorr_half(E[s], E[o]))
//   ccorr_half: out[k] = sum_i a[k + i - d/2] * b[i], zero-padded, d = 201
//   => eta = sum_k r[k] * sum_i a[k+i-100] * b[i]
//
// Inputs (metadata order): x [32,3] int32, E [1e6,201] f32, R [1e4,201] f32.
// Output: 1 float.
//
// Single block, 256 threads. Stage the three 201-float rows in shared memory,
// each thread k<201 computes one correlation tap weighted by r[k], then block
// reduce. Work is ~40K FMAs total — entirely latency/launch bound.

#define D 201
#define HALF 100   // D / 2

__global__ __launch_bounds__(256, 1)
void holo_kernel(const int* __restrict__ x,
                 const float* __restrict__ E,
                 const float* __restrict__ R,
                 float* __restrict__ out)
{
    __shared__ float sa[D];   // E[s]
    __shared__ float sb[D];   // E[o]
    __shared__ float sr[D];   // R[p]
    __shared__ float red[256];

    const int tid = threadIdx.x;

    // Row 0 of x: s, o, p
    const int s = x[0];
    const int o = x[1];
    const int p = x[2];

    const float* __restrict__ arow = E + (long long)s * D;
    const float* __restrict__ brow = E + (long long)o * D;
    const float* __restrict__ rrow = R + (long long)p * D;

    if (tid < D) {
        sa[tid] = arow[tid];
        sb[tid] = brow[tid];
        sr[tid] = rrow[tid];
    }
    __syncthreads();

    float partial = 0.0f;
    if (tid < D) {
        const int k = tid;
        // out[k] = sum_i a[k+i-100] * b[i] over valid i
        // valid: 0 <= k+i-100 < D  =>  i in [max(0,100-k), min(D, D+100-k))
        const int i_lo = (k < HALF) ? (HALF - k) : 0;
        const int i_hi = (k > HALF) ? (D + HALF - k) : D;
        float acc = 0.0f;
        const int base = k - HALF;
        #pragma unroll 4
        for (int i = i_lo; i < i_hi; ++i) {
            acc = fmaf(sa[base + i], sb[i], acc);
        }
        partial = sr[k] * acc;
    }

    // Block reduction (256 threads)
    red[tid] = partial;
    __syncthreads();
    #pragma unroll
    for (int stride = 128; stride >= 32; stride >>= 1) {
        if (tid < stride) red[tid] += red[tid + stride];
        __syncthreads();
    }
    if (tid < 32) {
        float v = red[tid];
        #pragma unroll
        for (int off = 16; off > 0; off >>= 1)
            v += __shfl_down_sync(0xFFFFFFFFu, v, off);
        if (tid == 0) out[0] = v;
    }
}

extern "C" void kernel_launch(void* const* d_in, const int* in_sizes, int n_in,
                              void* d_out, int out_size)
{
    const int*   x = (const int*)d_in[0];
    const float* E = (const float*)d_in[1];
    const float* R = (const float*)d_in[2];
    float* out = (float*)d_out;

    holo_kernel<<<1, 256>>>(x, E, R, out);
}

// round 4
// speedup vs baseline: 1.3478x; 1.3478x over previous
#include <cuda_runtime.h>
#include <cuda_bf16.h>

// HolographicLayer: eta = dot(R[p], ccorr_half(E[s], E[o]))
//   ccorr_half: out[k] = sum_i a[k + i - 100] * b[i], zero-padded, d = 201
//
// Register-blocked uniform kernel:
//   sa_pad[j] = a[j-100] for j in [100,301), else 0   (size 464, 16B aligned)
//   sb_pad[i] = b[i]     for i in [0,201),  else 0   (size 208)
//   r_pad [k] = r[k]     for k in [0,201),  else 0   (size 256)
//   out[k] = sum_{i=0..207} sa_pad[k+i]*sb_pad[i]  (padding => exact)
//
// 256 threads: t_k = tid&63 handles taps k0=4*t_k..k0+3 ; t_i = tid>>6 handles
// i-chunks [52*t_i, 52*t_i+52). All float4 accesses aligned (k0,i0 ≡ 0 mod 4).
// Every thread does identical work; pad zeros absorb out-of-range taps.

#define D 201

__global__ __launch_bounds__(256, 1)
void holo_kernel(const int* __restrict__ x,
                 const float* __restrict__ E,
                 const float* __restrict__ R,
                 float* __restrict__ out)
{
    __shared__ __align__(16) float sa_pad[464];
    __shared__ __align__(16) float sb_pad[208];
    __shared__ __align__(16) float r_pad[256];
    __shared__ float wred[8];

    const int tid = threadIdx.x;

    // Indices (row 0 of x): s, o, p
    const int s = __ldg(&x[0]);
    const int o = __ldg(&x[1]);
    const int p = __ldg(&x[2]);

    const float* __restrict__ arow = E + (long long)s * D;
    const float* __restrict__ brow = E + (long long)o * D;
    const float* __restrict__ rrow = R + (long long)p * D;

    // Zero-padded staging (single pass, values identical on overlap)
    {
        int j0 = tid;           // 0..255
        int j1 = tid + 208;     // 208..463
        sa_pad[j0] = (j0 >= 100 && j0 < 100 + D) ? __ldg(&arow[j0 - 100]) : 0.0f;
        sa_pad[j1] = (j1 < 100 + D) ? __ldg(&arow[j1 - 100]) : 0.0f;
        if (tid < 208)
            sb_pad[tid] = (tid < D) ? __ldg(&brow[tid]) : 0.0f;
        r_pad[tid] = (tid < D) ? __ldg(&rrow[tid]) : 0.0f;
    }
    __syncthreads();

    // Tile: 4 taps (k0..k0+3) x 52 i-values, rolling 8-float window, all aligned.
    const int k0    = (tid & 63) * 4;   // 0..252
    const int ibase = (tid >> 6) * 52;  // 0,52,104,156

    const float4* sa4 = (const float4*)sa_pad;
    const float4* sb4 = (const float4*)sb_pad;
    const int wbase = (k0 + ibase) >> 2;   // float4 index, aligned
    const int bbase = ibase >> 2;

    float acc0 = 0.0f, acc1 = 0.0f, acc2 = 0.0f, acc3 = 0.0f;
    float4 wa = sa4[wbase];
    #pragma unroll
    for (int cc = 0; cc < 13; ++cc) {
        const float4 wb = sa4[wbase + cc + 1];
        const float4 bv = sb4[bbase + cc];
        const float w0 = wa.x, w1 = wa.y, w2 = wa.z, w3 = wa.w;
        const float w4 = wb.x, w5 = wb.y, w6 = wb.z;
        acc0 = fmaf(w0, bv.x, acc0); acc0 = fmaf(w1, bv.y, acc0);
        acc0 = fmaf(w2, bv.z, acc0); acc0 = fmaf(w3, bv.w, acc0);
        acc1 = fmaf(w1, bv.x, acc1); acc1 = fmaf(w2, bv.y, acc1);
        acc1 = fmaf(w3, bv.z, acc1); acc1 = fmaf(w4, bv.w, acc1);
        acc2 = fmaf(w2, bv.x, acc2); acc2 = fmaf(w3, bv.y, acc2);
        acc2 = fmaf(w4, bv.z, acc2); acc2 = fmaf(w5, bv.w, acc2);
        acc3 = fmaf(w3, bv.x, acc3); acc3 = fmaf(w4, bv.y, acc3);
        acc3 = fmaf(w5, bv.z, acc3); acc3 = fmaf(w6, bv.w, acc3);
        wa = wb;
    }

    // Weight by r[k] and reduce
    float partial = r_pad[k0]     * acc0
                  + r_pad[k0 + 1] * acc1
                  + r_pad[k0 + 2] * acc2
                  + r_pad[k0 + 3] * acc3;

    // Warp reduce (8 full warps, no divergence)
    #pragma unroll
    for (int off = 16; off > 0; off >>= 1)
        partial += __shfl_xor_sync(0xFFFFFFFFu, partial, off);

    if ((tid & 31) == 0) wred[tid >> 5] = partial;
    __syncthreads();

    if (tid < 8) {
        float v = wred[tid];
        v += __shfl_xor_sync(0x000000FFu, v, 4);
        v += __shfl_xor_sync(0x000000FFu, v, 2);
        v += __shfl_xor_sync(0x000000FFu, v, 1);
        if (tid == 0) out[0] = v;
    }
}

extern "C" void kernel_launch(void* const* d_in, const int* in_sizes, int n_in,
                              void* d_out, int out_size)
{
    const int*   x = (const int*)d_in[0];
    const float* E = (const float*)d_in[1];
    const float* R = (const float*)d_in[2];
    float* out = (float*)d_out;

    holo_kernel<<<1, 256>>>(x, E, R, out);
}